// round 16
// baseline (speedup 1.0000x reference)
#include <cuda_runtime.h>
#include <math.h>

#define Hn     8
#define Nn     512
#define Dn     64
#define DNn    128
#define DEn    64
#define INNERn 512

typedef unsigned long long ull;

__device__ __forceinline__ ull pk2(float lo, float hi) {
    ull r; asm("mov.b64 %0,{%1,%2};" : "=l"(r) : "f"(lo), "f"(hi)); return r;
}
__device__ __forceinline__ float2 upk2(ull v) {
    float2 r; asm("mov.b64 {%0,%1},%2;" : "=f"(r.x), "=f"(r.y) : "l"(v)); return r;
}
__device__ __forceinline__ void fma2(ull& d, ull a, ull b) {
    asm("fma.rn.f32x2 %0,%1,%2,%3;" : "=l"(d) : "l"(a), "l"(b), "l"(d));
}

#define EROT(r) ((((r) >> 3) & 3) << 3)

// ---------------- scratch ----------------
__device__ float g_q  [Hn * Nn * Dn];
__device__ float g_k  [Hn * Nn * Dn];
__device__ float g_v  [Hn * Nn * Dn];
__device__ float g_qe [Hn * Nn * DEn];
__device__ float g_qbe[Hn * Nn];
__device__ float g_sim[Hn * Nn * Nn];    // qk logits, then NORMALIZED p
__device__ float g_ew [Hn * Nn * DEn];   // normalized
__device__ float g_M  [INNERn * DNn];
__device__ float g_VW [Hn * Nn * DNn];
__device__ float g_bvec[DNn];
__device__ float g_part[16 * Nn * DNn];

// ================= kernel A: qkv + M + bvec (449 blocks) =================
__global__ void __launch_bounds__(256)
qkv_mb_kernel(const float* __restrict__ nodes,
              const float* __restrict__ Wq, const float* __restrict__ bq,
              const float* __restrict__ Wk, const float* __restrict__ bk,
              const float* __restrict__ Wv, const float* __restrict__ bv,
              const float* __restrict__ We, const float* __restrict__ be,
              const float* __restrict__ Wo, const float* __restrict__ bo)
{
    __shared__ float smbuf[12288];
    const int b = blockIdx.x;
    const int t = threadIdx.x;

    if (b < 384) {
        float (*sN)[DNn] = (float(*)[DNn])smbuf;
        float (*sW)[64]  = (float(*)[64])(smbuf + 4096);

        const int it = b & 15;
        const int ct = b >> 4;
        const int mat = ct >> 3;
        const int h   = ct & 7;
        const int colbase = h * 64;
        const float* W    = (mat == 0) ? Wq : (mat == 1 ? Wk : Wv);
        const float* bias = (mat == 0) ? bq : (mat == 1 ? bk : bv);
        float* out        = (mat == 0) ? g_q : (mat == 1 ? g_k : g_v);
        const int i0 = it * 32;

        {
            const float4* nf = (const float4*)(nodes + (size_t)i0 * DNn);
            float4* sNf = (float4*)&sN[0][0];
            #pragma unroll
            for (int r = 0; r < 4; r++) sNf[t + 256 * r] = nf[t + 256 * r];
        }
        #pragma unroll
        for (int r = 0; r < 8; r++) {
            int idx = t + 256 * r;
            int f = idx >> 4, c4 = idx & 15;
            ((float4*)&sW[f][0])[c4] = *(const float4*)(W + (size_t)f * INNERn + colbase + c4 * 4);
        }
        __syncthreads();

        const int col   = t & 63;
        const int ibase = t >> 6;
        float acc[8];
        #pragma unroll
        for (int r = 0; r < 8; r++) acc[r] = 0.f;

        #pragma unroll 2
        for (int f4 = 0; f4 < 32; f4++) {
            float w0 = sW[f4 * 4 + 0][col];
            float w1 = sW[f4 * 4 + 1][col];
            float w2 = sW[f4 * 4 + 2][col];
            float w3 = sW[f4 * 4 + 3][col];
            #pragma unroll
            for (int r = 0; r < 8; r++) {
                float4 nv = *(const float4*)&sN[ibase + 4 * r][f4 * 4];
                acc[r] += nv.x * w0 + nv.y * w1 + nv.z * w2 + nv.w * w3;
            }
        }

        const float bb = bias[colbase + col];
        const float sc = (mat == 0) ? 0.125f : 1.0f;
        float vals[8];
        #pragma unroll
        for (int r = 0; r < 8; r++) {
            vals[r] = (acc[r] + bb) * sc;
            int i = i0 + ibase + 4 * r;
            out[(size_t)h * (Nn * Dn) + (size_t)i * Dn + col] = vals[r];
        }

        if (mat == 0) {
            float (*sOut)[Dn] = (float(*)[Dn])&sW[0][0];
            __syncthreads();
            #pragma unroll
            for (int r = 0; r < 8; r++) sOut[ibase + 4 * r][col] = vals[r];
            __syncthreads();

            float wreg[Dn];
            #pragma unroll
            for (int d = 0; d < Dn; d++) wreg[d] = We[(size_t)col * INNERn + colbase + d];
            #pragma unroll
            for (int r = 0; r < 8; r++) {
                int i = i0 + ibase + 4 * r;
                float s = 0.f;
                #pragma unroll
                for (int d = 0; d < Dn; d++) s += wreg[d] * sOut[ibase + 4 * r][d];
                g_qe[(size_t)h * (Nn * DEn) + (size_t)i * DEn + col] = s;
            }
            if (col == 0) {
                #pragma unroll
                for (int r = 0; r < 8; r++) {
                    int i = i0 + ibase + 4 * r;
                    float sb = 0.f;
                    for (int d = 0; d < 64; d++) sb += sOut[ibase + 4 * r][d] * be[colbase + d];
                    g_qbe[h * Nn + i] = sb;
                }
            }
        }
    } else if (b < 448) {
        const int wb = b - 384;
        const int h  = wb >> 3;
        const int c0 = (wb & 7) * 8 + (t >> 7) * 4;
        const int o  = t & 127;
        float acc[4] = {0.f, 0.f, 0.f, 0.f};
        #pragma unroll 4
        for (int d = 0; d < 64; d++) {
            float wo = Wo[(size_t)(h * 64 + d) * DNn + o];
            #pragma unroll
            for (int cc = 0; cc < 4; cc++)
                acc[cc] += We[(size_t)(c0 + cc) * INNERn + h * 64 + d] * wo;
        }
        #pragma unroll
        for (int cc = 0; cc < 4; cc++)
            g_M[(size_t)(h * 64 + c0 + cc) * DNn + o] = acc[cc];
    } else {
        float* sRed = smbuf;
        const int col = t & 127;
        const int ks  = t >> 7;
        float acc = 0.f;
        #pragma unroll 8
        for (int k = ks * 256; k < ks * 256 + 256; k++)
            acc += be[k] * Wo[(size_t)k * DNn + col];
        sRed[t] = acc;
        __syncthreads();
        if (t < 128) g_bvec[t] = sRed[t] + sRed[t + 128] + bo[t];
    }
}

// ================= kernel B: qksim + VW (640 blocks) =================
__global__ void __launch_bounds__(256)
qksim_vw_kernel(const float* __restrict__ Wo)
{
    __shared__ float smbuf[10752];
    const int b = blockIdx.x;
    const int t = threadIdx.x;

    if (b < 512) {
        float (*sQT)[36]  = (float(*)[36])smbuf;
        float (*sKT)[132] = (float(*)[132])(smbuf + 2304);

        const int i0 = (b & 15) * 32;
        const int j0 = ((b >> 4) & 3) * 128;
        const int h  = b >> 6;

        #pragma unroll
        for (int r = 0; r < 2; r++) {
            int idx = t + 256 * r;
            int i = idx >> 4, d4 = (idx & 15) * 4;
            float4 v = *(const float4*)(g_q + (size_t)h * (Nn * Dn) + (size_t)(i0 + i) * Dn + d4);
            sQT[d4 + 0][i] = v.x; sQT[d4 + 1][i] = v.y; sQT[d4 + 2][i] = v.z; sQT[d4 + 3][i] = v.w;
        }
        #pragma unroll
        for (int r = 0; r < 8; r++) {
            int idx = t + 256 * r;
            int j = idx >> 4, d4 = (idx & 15) * 4;
            float4 v = *(const float4*)(g_k + (size_t)h * (Nn * Dn) + (size_t)(j0 + j) * Dn + d4);
            sKT[d4 + 0][j] = v.x; sKT[d4 + 1][j] = v.y; sKT[d4 + 2][j] = v.z; sKT[d4 + 3][j] = v.w;
        }
        __syncthreads();

        const int ii0 = (t >> 5) * 4;
        const int jj0 = (t & 31) * 4;
        ull acc[4][2];
        #pragma unroll
        for (int u = 0; u < 4; u++) { acc[u][0] = 0ull; acc[u][1] = 0ull; }

        #pragma unroll 4
        for (int d = 0; d < 64; d++) {
            float4 rq = *(const float4*)&sQT[d][ii0];
            ulonglong2 rk = *(const ulonglong2*)&sKT[d][jj0];
            ull a;
            a = pk2(rq.x, rq.x); fma2(acc[0][0], a, rk.x); fma2(acc[0][1], a, rk.y);
            a = pk2(rq.y, rq.y); fma2(acc[1][0], a, rk.x); fma2(acc[1][1], a, rk.y);
            a = pk2(rq.z, rq.z); fma2(acc[2][0], a, rk.x); fma2(acc[2][1], a, rk.y);
            a = pk2(rq.w, rq.w); fma2(acc[3][0], a, rk.x); fma2(acc[3][1], a, rk.y);
        }

        #pragma unroll
        for (int u = 0; u < 4; u++) {
            float qbe = g_qbe[h * Nn + i0 + ii0 + u];
            float2 lo = upk2(acc[u][0]);
            float2 hi = upk2(acc[u][1]);
            float4 o = make_float4(lo.x + qbe, lo.y + qbe, hi.x + qbe, hi.y + qbe);
            *(float4*)(g_sim + ((size_t)(h * Nn + i0 + ii0 + u)) * Nn + j0 + jj0) = o;
        }
    } else {
        float (*sV)[68]   = (float(*)[68])smbuf;
        float (*sWo)[132] = (float(*)[132])(smbuf + 2176);

        const int vb = b - 512;
        const int h  = vb >> 4;
        const int j0 = (vb & 15) * 32;
        #pragma unroll
        for (int u = 0; u < 2; u++) {
            int idx = t + 256 * u;
            int j = idx >> 4, d4 = (idx & 15) * 4;
            *(float4*)&sV[j][d4] = *(const float4*)(g_v + (size_t)h * (Nn * Dn) + (size_t)(j0 + j) * Dn + d4);
        }
        #pragma unroll
        for (int u = 0; u < 8; u++) {
            int idx = t + 256 * u;
            int d = idx >> 5, o4 = (idx & 31) * 4;
            *(float4*)&sWo[d][o4] = *(const float4*)(Wo + (size_t)(h * 64 + d) * DNn + o4);
        }
        __syncthreads();

        const int jj0 = (t >> 5) * 4;
        const int oo0 = (t & 31) * 4;
        float acc[4][4];
        #pragma unroll
        for (int u = 0; u < 4; u++)
            #pragma unroll
            for (int v = 0; v < 4; v++) acc[u][v] = 0.f;

        #pragma unroll 4
        for (int d = 0; d < 64; d++) {
            float a0 = sV[jj0 + 0][d], a1 = sV[jj0 + 1][d], a2 = sV[jj0 + 2][d], a3 = sV[jj0 + 3][d];
            float4 w = *(const float4*)&sWo[d][oo0];
            acc[0][0] += a0 * w.x; acc[0][1] += a0 * w.y; acc[0][2] += a0 * w.z; acc[0][3] += a0 * w.w;
            acc[1][0] += a1 * w.x; acc[1][1] += a1 * w.y; acc[1][2] += a1 * w.z; acc[1][3] += a1 * w.w;
            acc[2][0] += a2 * w.x; acc[2][1] += a2 * w.y; acc[2][2] += a2 * w.z; acc[2][3] += a2 * w.w;
            acc[3][0] += a3 * w.x; acc[3][1] += a3 * w.y; acc[3][2] += a3 * w.z; acc[3][3] += a3 * w.w;
        }
        #pragma unroll
        for (int u = 0; u < 4; u++) {
            float4 o4 = make_float4(acc[u][0], acc[u][1], acc[u][2], acc[u][3]);
            *(float4*)(g_VW + (size_t)(h * Nn + j0 + jj0 + u) * DNn + oo0) = o4;
        }
    }
}

// ================= kernel C: edge_mega v3 (unchanged) =================
#define EMS_SIM  0
#define EMS_QEP  4096
#define EMS_SINV 4608
#define EMS_RED  4624
#define EMS_E    8720
#define EM_SMEM  ((EMS_E + 64 * 68 + 32) * 4)

__global__ void __launch_bounds__(256, 4)
edge_mega_kernel(const float* __restrict__ edges)
{
    extern __shared__ float sm[];
    float* sSim  = sm + EMS_SIM;
    ull*   sQEP  = (ull*)(sm + EMS_QEP);
    float* sSinv = sm + EMS_SINV;
    ull*   sRed  = (ull*)(sm + EMS_RED);
    float* sE    = sm + EMS_E;

    const int i = blockIdx.x;
    const int t = threadIdx.x;
    const int w = t >> 5, l = t & 31;

    #pragma unroll
    for (int r = 0; r < 4; r++) {
        int idx = t + 256 * r;
        int h = idx >> 7, j4 = (idx & 127) * 4;
        *(float4*)&sSim[h * 512 + j4] = *(const float4*)(g_sim + ((size_t)(h * Nn + i)) * Nn + j4);
    }
    {
        int c = t >> 2, hp = t & 3;
        float a = g_qe[(size_t)(2 * hp)     * (Nn * DEn) + (size_t)i * DEn + c];
        float b = g_qe[(size_t)(2 * hp + 1) * (Nn * DEn) + (size_t)i * DEn + c];
        sQEP[c * 4 + hp] = pk2(a, b);
    }
    __syncthreads();

    const int ce0 = w * 8;
    const int rot0 = EROT(l);

    for (int tile = 0; tile < 8; tile++) {
        const int j0 = tile * 64;
        #pragma unroll
        for (int u = 0; u < 4; u++) {
            int idx = t + 256 * u;
            int row = idx >> 4, s4 = (idx & 15) * 4;
            *(float4*)&sE[row * 68 + ((s4 + EROT(row)) & 63)] =
                *(const float4*)(edges + ((size_t)i * Nn + j0 + row) * DEn + s4);
        }
        __syncthreads();

        ull a0[4] = {0, 0, 0, 0}, a1[4] = {0, 0, 0, 0};
        #pragma unroll
        for (int cc = 0; cc < 2; cc++) {
            const int cb = ce0 + cc * 4;
            const int co = (cb + rot0) & 63;
            float4 e0 = *(const float4*)&sE[l * 68 + co];
            float4 e1 = *(const float4*)&sE[(l + 32) * 68 + co];
            float e0a[4] = {e0.x, e0.y, e0.z, e0.w};
            float e1a[4] = {e1.x, e1.y, e1.z, e1.w};
            #pragma unroll
            for (int k = 0; k < 4; k++) {
                ulonglong2 q01 = *(const ulonglong2*)&sQEP[(cb + k) * 4];
                ulonglong2 q23 = *(const ulonglong2*)&sQEP[(cb + k) * 4 + 2];
                ull ed0 = pk2(e0a[k], e0a[k]);
                ull ed1 = pk2(e1a[k], e1a[k]);
                fma2(a0[0], ed0, q01.x); fma2(a0[1], ed0, q01.y);
                fma2(a0[2], ed0, q23.x); fma2(a0[3], ed0, q23.y);
                fma2(a1[0], ed1, q01.x); fma2(a1[1], ed1, q01.y);
                fma2(a1[2], ed1, q23.x); fma2(a1[3], ed1, q23.y);
            }
        }
        #pragma unroll
        for (int hp = 0; hp < 4; hp++) {
            sRed[w * 256 + hp * 64 + l]      = a0[hp];
            sRed[w * 256 + hp * 64 + l + 32] = a1[hp];
        }
        __syncthreads();

        {
            const int rr = t & 63, hp2 = t >> 6;
            float ax = 0.f, ay = 0.f;
            #pragma unroll
            for (int qq = 0; qq < 8; qq++) {
                float2 f = upk2(sRed[qq * 256 + hp2 * 64 + rr]);
                ax += f.x; ay += f.y;
            }
            sSim[(2 * hp2) * 512 + j0 + rr]     += ax;
            sSim[(2 * hp2 + 1) * 512 + j0 + rr] += ay;
        }
        __syncthreads();
    }

    {
        float vals[16];
        float mx = -1e30f;
        #pragma unroll
        for (int jc = 0; jc < 16; jc++) {
            vals[jc] = sSim[w * 512 + jc * 32 + l];
            mx = fmaxf(mx, vals[jc]);
        }
        #pragma unroll
        for (int off = 16; off > 0; off >>= 1) mx = fmaxf(mx, __shfl_xor_sync(0xffffffffu, mx, off));
        float s = 0.f;
        #pragma unroll
        for (int jc = 0; jc < 16; jc++) {
            float e = __expf(vals[jc] - mx);
            s += e;
            sSim[w * 512 + jc * 32 + l] = e;
        }
        #pragma unroll
        for (int off = 16; off > 0; off >>= 1) s += __shfl_xor_sync(0xffffffffu, s, off);
        if (l == 0) sSinv[w] = 1.0f / s;
    }
    __syncthreads();

    #pragma unroll
    for (int r = 0; r < 4; r++) {
        int idx = t + 256 * r;
        int h = idx >> 7, j4 = (idx & 127) * 4;
        float4 v = *(const float4*)&sSim[h * 512 + j4];
        float s = sSinv[h];
        v.x *= s; v.y *= s; v.z *= s; v.w *= s;
        *(float4*)(g_sim + ((size_t)(h * Nn + i)) * Nn + j4) = v;
    }

    {
        float pr[16];
        #pragma unroll
        for (int h = 0; h < 8; h++) {
            pr[h]     = sSim[h * 512 + t];
            pr[8 + h] = sSim[h * 512 + t + 256];
        }
        __syncthreads();
        ull* sPP = (ull*)sSim;
        #pragma unroll
        for (int hp = 0; hp < 4; hp++) {
            sPP[t * 4 + hp]         = pk2(pr[2 * hp],     pr[2 * hp + 1]);
            sPP[(t + 256) * 4 + hp] = pk2(pr[8 + 2 * hp], pr[8 + 2 * hp + 1]);
        }
    }
    __syncthreads();

    {
        ull* sPP = (ull*)sSim;
        ull acc[4][2];
        #pragma unroll
        for (int hp = 0; hp < 4; hp++) { acc[hp][0] = 0ull; acc[hp][1] = 0ull; }

        for (int tile = 0; tile < 8; tile++) {
            const int j0 = tile * 64;
            #pragma unroll
            for (int u = 0; u < 4; u++) {
                int idx = t + 256 * u;
                int row = idx >> 4, s4 = (idx & 15) * 4;
                *(float4*)&sE[row * 68 + ((s4 + EROT(row)) & 63)] =
                    *(const float4*)(edges + ((size_t)i * Nn + j0 + row) * DEn + s4);
            }
            __syncthreads();

            const int jb = w * 8;
            #pragma unroll
            for (int jj = 0; jj < 8; jj++) {
                const int j = jb + jj;
                ull e2 = *(const ull*)&sE[j * 68 + ((2 * l + EROT(j)) & 63)];
                float2 ef = upk2(e2);
                ull e0 = pk2(ef.x, ef.x);
                ull e1 = pk2(ef.y, ef.y);
                const ull* pp = sPP + (size_t)(j0 + j) * 4;
                fma2(acc[0][0], pp[0], e0); fma2(acc[0][1], pp[0], e1);
                fma2(acc[1][0], pp[1], e0); fma2(acc[1][1], pp[1], e1);
                fma2(acc[2][0], pp[2], e0); fma2(acc[2][1], pp[2], e1);
                fma2(acc[3][0], pp[3], e0); fma2(acc[3][1], pp[3], e1);
            }
            __syncthreads();
        }

        #pragma unroll
        for (int hp = 0; hp < 4; hp++) {
            sRed[w * 256 + l * 8 + hp * 2 + 0] = acc[hp][0];
            sRed[w * 256 + l * 8 + hp * 2 + 1] = acc[hp][1];
        }
        __syncthreads();

        {
            float ax = 0.f, ay = 0.f;
            #pragma unroll
            for (int ww = 0; ww < 8; ww++) {
                float2 f = upk2(sRed[ww * 256 + t]);
                ax += f.x; ay += f.y;
            }
            const int c  = 2 * (t >> 3) + (t & 1);
            const int h0 = 2 * ((t >> 1) & 3);
            g_ew[(size_t)h0       * (Nn * DEn) + (size_t)i * DEn + c] = ax * sSinv[h0];
            g_ew[(size_t)(h0 + 1) * (Nn * DEn) + (size_t)i * DEn + c] = ay * sSinv[h0 + 1];
        }
    }
}

// ================= kernel D: epilogue GEMM v6 (dup-A, grid 16x16) ====
// sAd: 32 rows x 66 ull (pre-duplicated A). sB: 64 x 132 floats.
#define G6_B (32 * 66 * 2)            // float offset of sB
#define G6_SMEM ((G6_B + 64 * 132) * 4)

__global__ void __launch_bounds__(256)
gemm_out_kernel()
{
    extern __shared__ float gsm[];
    ull*   sAd = (ull*)gsm;           // [32][66] ull
    float* sB  = gsm + G6_B;

    const int t  = threadIdx.x;
    const int i0 = blockIdx.x * 32;
    const int h  = blockIdx.y >> 1;
    const int kh = blockIdx.y & 1;

    const int warp = t >> 5, lane = t & 31;
    const int ib = warp * 4;
    const int ob = lane * 4;

    ull acc[4][2];
    #pragma unroll
    for (int r = 0; r < 4; r++) { acc[r][0] = 0ull; acc[r][1] = 0ull; }

    const int kcs = kh ? 4 : 0;
    const int kce = kh ? 9 : 4;
    for (int kc = kcs; kc < kce; kc++) {
        // A tile: 32 x 64, stored duplicated
        #pragma unroll
        for (int u = 0; u < 2; u++) {
            int idx = t + 256 * u;
            int i = idx >> 4, k4 = (idx & 15) * 4;
            float4 v;
            if (kc < 8)
                v = *(const float4*)(g_sim + ((size_t)(h * Nn + i0 + i)) * Nn + kc * 64 + k4);
            else
                v = *(const float4*)(g_ew + (size_t)h * (Nn * DEn) + (size_t)(i0 + i) * DEn + k4);
            ull* d = sAd + i * 66 + k4;
            d[0] = pk2(v.x, v.x);
            d[1] = pk2(v.y, v.y);
            d[2] = pk2(v.z, v.z);
            d[3] = pk2(v.w, v.w);
        }
        // B tile: 64 x 128
        #pragma unroll
        for (int u = 0; u < 8; u++) {
            int idx = t + 256 * u;
            int k = idx >> 5, o4 = (idx & 31) * 4;
            float4 v;
            if (kc < 8) v = *(const float4*)(g_VW + ((size_t)(h * Nn + kc * 64 + k)) * DNn + o4);
            else        v = *(const float4*)(g_M + ((size_t)(h * 64 + k)) * DNn + o4);
            *(float4*)&sB[k * 132 + o4] = v;
        }
        __syncthreads();

        #pragma unroll 4
        for (int k = 0; k < 64; k++) {
            ulonglong2 bv = *(const ulonglong2*)&sB[k * 132 + ob];
            #pragma unroll
            for (int r = 0; r < 4; r++) {
                ull ad = sAd[(ib + r) * 66 + k];   // warp-uniform broadcast
                fma2(acc[r][0], ad, bv.x);
                fma2(acc[r][1], ad, bv.y);
            }
        }
        __syncthreads();
    }

    float* pp = g_part + (size_t)blockIdx.y * (Nn * DNn);
    #pragma unroll
    for (int r = 0; r < 4; r++) {
        float2 f0 = upk2(acc[r][0]);
        float2 f1 = upk2(acc[r][1]);
        *(float2*)(pp + (size_t)(i0 + ib + r) * DNn + ob)     = f0;
        *(float2*)(pp + (size_t)(i0 + ib + r) * DNn + ob + 2) = f1;
    }
}

// ================= kernel E: reduce 16 partials + bvec =================
__global__ void __launch_bounds__(256)
reduce_out_kernel(float* __restrict__ out)
{
    const int idx = blockIdx.x * 256 + threadIdx.x;
    float a0 = 0.f, a1 = 0.f, a2 = 0.f, a3 = 0.f;
    #pragma unroll
    for (int s = 0; s < 16; s += 4) {
        a0 += g_part[(size_t)s       * (Nn * DNn) + idx];
        a1 += g_part[(size_t)(s + 1) * (Nn * DNn) + idx];
        a2 += g_part[(size_t)(s + 2) * (Nn * DNn) + idx];
        a3 += g_part[(size_t)(s + 3) * (Nn * DNn) + idx];
    }
    out[idx] = (a0 + a1) + (a2 + a3) + g_bvec[idx & 127];
}

// ---------------- launch ----------------
extern "C" void kernel_launch(void* const* d_in, const int* in_sizes, int n_in,
                              void* d_out, int out_size)
{
    const float* nodes = (const float*)d_in[0];
    const float* edges = (const float*)d_in[1];
    const float* Wq = (const float*)d_in[3];
    const float* bq = (const float*)d_in[4];
    const float* Wk = (const float*)d_in[5];
    const float* bk = (const float*)d_in[6];
    const float* Wv = (const float*)d_in[7];
    const float* bv = (const float*)d_in[8];
    const float* We = (const float*)d_in[9];
    const float* be = (const float*)d_in[10];
    const float* Wo = (const float*)d_in[11];
    const float* bo = (const float*)d_in[12];
    float* out = (float*)d_out;

    cudaFuncSetAttribute(edge_mega_kernel, cudaFuncAttributeMaxDynamicSharedMemorySize, EM_SMEM);
    cudaFuncSetAttribute(gemm_out_kernel, cudaFuncAttributeMaxDynamicSharedMemorySize, G6_SMEM);

    qkv_mb_kernel<<<449, 256>>>(nodes, Wq, bq, Wk, bk, Wv, bv, We, be, Wo, bo);
    qksim_vw_kernel<<<640, 256>>>(Wo);
    edge_mega_kernel<<<Nn, 256, EM_SMEM>>>(edges);
    gemm_out_kernel<<<dim3(16, 16), 256, G6_SMEM>>>();
    reduce_out_kernel<<<(Nn * DNn) / 256, 256>>>(out);
}

// round 17
// speedup vs baseline: 1.0568x; 1.0568x over previous
#include <cuda_runtime.h>
#include <math.h>

#define Hn     8
#define Nn     512
#define Dn     64
#define DNn    128
#define DEn    64
#define INNERn 512

typedef unsigned long long ull;

__device__ __forceinline__ ull pk2(float lo, float hi) {
    ull r; asm("mov.b64 %0,{%1,%2};" : "=l"(r) : "f"(lo), "f"(hi)); return r;
}
__device__ __forceinline__ float2 upk2(ull v) {
    float2 r; asm("mov.b64 {%0,%1},%2;" : "=f"(r.x), "=f"(r.y) : "l"(v)); return r;
}
__device__ __forceinline__ void fma2(ull& d, ull a, ull b) {
    asm("fma.rn.f32x2 %0,%1,%2,%3;" : "=l"(d) : "l"(a), "l"(b), "l"(d));
}

#define EROT(r) ((((r) >> 3) & 3) << 3)

// ---------------- scratch ----------------
__device__ float g_q  [Hn * Nn * Dn];
__device__ float g_k  [Hn * Nn * Dn];
__device__ float g_v  [Hn * Nn * Dn];
__device__ float g_qe [Hn * Nn * DEn];
__device__ float g_qbe[Hn * Nn];
__device__ float g_sim[Hn * Nn * Nn];    // qk logits, then NORMALIZED p
__device__ float g_ew [Hn * Nn * DEn];   // normalized
__device__ float g_M  [INNERn * DNn];
__device__ float g_VW [Hn * Nn * DNn];
__device__ float g_bvec[DNn];
__device__ float g_part[16 * Nn * DNn];

// ================= kernel A: qkv + M + bvec (449 blocks) =================
__global__ void __launch_bounds__(256)
qkv_mb_kernel(const float* __restrict__ nodes,
              const float* __restrict__ Wq, const float* __restrict__ bq,
              const float* __restrict__ Wk, const float* __restrict__ bk,
              const float* __restrict__ Wv, const float* __restrict__ bv,
              const float* __restrict__ We, const float* __restrict__ be,
              const float* __restrict__ Wo, const float* __restrict__ bo)
{
    __shared__ float smbuf[12288];
    const int b = blockIdx.x;
    const int t = threadIdx.x;

    if (b < 384) {
        float (*sN)[DNn] = (float(*)[DNn])smbuf;
        float (*sW)[64]  = (float(*)[64])(smbuf + 4096);

        const int it = b & 15;
        const int ct = b >> 4;
        const int mat = ct >> 3;
        const int h   = ct & 7;
        const int colbase = h * 64;
        const float* W    = (mat == 0) ? Wq : (mat == 1 ? Wk : Wv);
        const float* bias = (mat == 0) ? bq : (mat == 1 ? bk : bv);
        float* out        = (mat == 0) ? g_q : (mat == 1 ? g_k : g_v);
        const int i0 = it * 32;

        {
            const float4* nf = (const float4*)(nodes + (size_t)i0 * DNn);
            float4* sNf = (float4*)&sN[0][0];
            #pragma unroll
            for (int r = 0; r < 4; r++) sNf[t + 256 * r] = nf[t + 256 * r];
        }
        #pragma unroll
        for (int r = 0; r < 8; r++) {
            int idx = t + 256 * r;
            int f = idx >> 4, c4 = idx & 15;
            ((float4*)&sW[f][0])[c4] = *(const float4*)(W + (size_t)f * INNERn + colbase + c4 * 4);
        }
        __syncthreads();

        const int col   = t & 63;
        const int ibase = t >> 6;
        float acc[8];
        #pragma unroll
        for (int r = 0; r < 8; r++) acc[r] = 0.f;

        #pragma unroll 2
        for (int f4 = 0; f4 < 32; f4++) {
            float w0 = sW[f4 * 4 + 0][col];
            float w1 = sW[f4 * 4 + 1][col];
            float w2 = sW[f4 * 4 + 2][col];
            float w3 = sW[f4 * 4 + 3][col];
            #pragma unroll
            for (int r = 0; r < 8; r++) {
                float4 nv = *(const float4*)&sN[ibase + 4 * r][f4 * 4];
                acc[r] += nv.x * w0 + nv.y * w1 + nv.z * w2 + nv.w * w3;
            }
        }

        const float bb = bias[colbase + col];
        const float sc = (mat == 0) ? 0.125f : 1.0f;
        float vals[8];
        #pragma unroll
        for (int r = 0; r < 8; r++) {
            vals[r] = (acc[r] + bb) * sc;
            int i = i0 + ibase + 4 * r;
            out[(size_t)h * (Nn * Dn) + (size_t)i * Dn + col] = vals[r];
        }

        if (mat == 0) {
            float (*sOut)[Dn] = (float(*)[Dn])&sW[0][0];
            __syncthreads();
            #pragma unroll
            for (int r = 0; r < 8; r++) sOut[ibase + 4 * r][col] = vals[r];
            __syncthreads();

            float wreg[Dn];
            #pragma unroll
            for (int d = 0; d < Dn; d++) wreg[d] = We[(size_t)col * INNERn + colbase + d];
            #pragma unroll
            for (int r = 0; r < 8; r++) {
                int i = i0 + ibase + 4 * r;
                float s = 0.f;
                #pragma unroll
                for (int d = 0; d < Dn; d++) s += wreg[d] * sOut[ibase + 4 * r][d];
                g_qe[(size_t)h * (Nn * DEn) + (size_t)i * DEn + col] = s;
            }
            if (col == 0) {
                #pragma unroll
                for (int r = 0; r < 8; r++) {
                    int i = i0 + ibase + 4 * r;
                    float sb = 0.f;
                    for (int d = 0; d < 64; d++) sb += sOut[ibase + 4 * r][d] * be[colbase + d];
                    g_qbe[h * Nn + i] = sb;
                }
            }
        }
    } else if (b < 448) {
        const int wb = b - 384;
        const int h  = wb >> 3;
        const int c0 = (wb & 7) * 8 + (t >> 7) * 4;
        const int o  = t & 127;
        float acc[4] = {0.f, 0.f, 0.f, 0.f};
        #pragma unroll 4
        for (int d = 0; d < 64; d++) {
            float wo = Wo[(size_t)(h * 64 + d) * DNn + o];
            #pragma unroll
            for (int cc = 0; cc < 4; cc++)
                acc[cc] += We[(size_t)(c0 + cc) * INNERn + h * 64 + d] * wo;
        }
        #pragma unroll
        for (int cc = 0; cc < 4; cc++)
            g_M[(size_t)(h * 64 + c0 + cc) * DNn + o] = acc[cc];
    } else {
        float* sRed = smbuf;
        const int col = t & 127;
        const int ks  = t >> 7;
        float acc = 0.f;
        #pragma unroll 8
        for (int k = ks * 256; k < ks * 256 + 256; k++)
            acc += be[k] * Wo[(size_t)k * DNn + col];
        sRed[t] = acc;
        __syncthreads();
        if (t < 128) g_bvec[t] = sRed[t] + sRed[t + 128] + bo[t];
    }
}

// ================= kernel B: qksim + VW (640 blocks) =================
__global__ void __launch_bounds__(256)
qksim_vw_kernel(const float* __restrict__ Wo)
{
    __shared__ float smbuf[10752];
    const int b = blockIdx.x;
    const int t = threadIdx.x;

    if (b < 512) {
        float (*sQT)[36]  = (float(*)[36])smbuf;
        float (*sKT)[132] = (float(*)[132])(smbuf + 2304);

        const int i0 = (b & 15) * 32;
        const int j0 = ((b >> 4) & 3) * 128;
        const int h  = b >> 6;

        #pragma unroll
        for (int r = 0; r < 2; r++) {
            int idx = t + 256 * r;
            int i = idx >> 4, d4 = (idx & 15) * 4;
            float4 v = *(const float4*)(g_q + (size_t)h * (Nn * Dn) + (size_t)(i0 + i) * Dn + d4);
            sQT[d4 + 0][i] = v.x; sQT[d4 + 1][i] = v.y; sQT[d4 + 2][i] = v.z; sQT[d4 + 3][i] = v.w;
        }
        #pragma unroll
        for (int r = 0; r < 8; r++) {
            int idx = t + 256 * r;
            int j = idx >> 4, d4 = (idx & 15) * 4;
            float4 v = *(const float4*)(g_k + (size_t)h * (Nn * Dn) + (size_t)(j0 + j) * Dn + d4);
            sKT[d4 + 0][j] = v.x; sKT[d4 + 1][j] = v.y; sKT[d4 + 2][j] = v.z; sKT[d4 + 3][j] = v.w;
        }
        __syncthreads();

        const int ii0 = (t >> 5) * 4;
        const int jj0 = (t & 31) * 4;
        ull acc[4][2];
        #pragma unroll
        for (int u = 0; u < 4; u++) { acc[u][0] = 0ull; acc[u][1] = 0ull; }

        #pragma unroll 4
        for (int d = 0; d < 64; d++) {
            float4 rq = *(const float4*)&sQT[d][ii0];
            ulonglong2 rk = *(const ulonglong2*)&sKT[d][jj0];
            ull a;
            a = pk2(rq.x, rq.x); fma2(acc[0][0], a, rk.x); fma2(acc[0][1], a, rk.y);
            a = pk2(rq.y, rq.y); fma2(acc[1][0], a, rk.x); fma2(acc[1][1], a, rk.y);
            a = pk2(rq.z, rq.z); fma2(acc[2][0], a, rk.x); fma2(acc[2][1], a, rk.y);
            a = pk2(rq.w, rq.w); fma2(acc[3][0], a, rk.x); fma2(acc[3][1], a, rk.y);
        }

        #pragma unroll
        for (int u = 0; u < 4; u++) {
            float qbe = g_qbe[h * Nn + i0 + ii0 + u];
            float2 lo = upk2(acc[u][0]);
            float2 hi = upk2(acc[u][1]);
            float4 o = make_float4(lo.x + qbe, lo.y + qbe, hi.x + qbe, hi.y + qbe);
            *(float4*)(g_sim + ((size_t)(h * Nn + i0 + ii0 + u)) * Nn + j0 + jj0) = o;
        }
    } else {
        float (*sV)[68]   = (float(*)[68])smbuf;
        float (*sWo)[132] = (float(*)[132])(smbuf + 2176);

        const int vb = b - 512;
        const int h  = vb >> 4;
        const int j0 = (vb & 15) * 32;
        #pragma unroll
        for (int u = 0; u < 2; u++) {
            int idx = t + 256 * u;
            int j = idx >> 4, d4 = (idx & 15) * 4;
            *(float4*)&sV[j][d4] = *(const float4*)(g_v + (size_t)h * (Nn * Dn) + (size_t)(j0 + j) * Dn + d4);
        }
        #pragma unroll
        for (int u = 0; u < 8; u++) {
            int idx = t + 256 * u;
            int d = idx >> 5, o4 = (idx & 31) * 4;
            *(float4*)&sWo[d][o4] = *(const float4*)(Wo + (size_t)(h * 64 + d) * DNn + o4);
        }
        __syncthreads();

        const int jj0 = (t >> 5) * 4;
        const int oo0 = (t & 31) * 4;
        float acc[4][4];
        #pragma unroll
        for (int u = 0; u < 4; u++)
            #pragma unroll
            for (int v = 0; v < 4; v++) acc[u][v] = 0.f;

        #pragma unroll 4
        for (int d = 0; d < 64; d++) {
            float a0 = sV[jj0 + 0][d], a1 = sV[jj0 + 1][d], a2 = sV[jj0 + 2][d], a3 = sV[jj0 + 3][d];
            float4 w = *(const float4*)&sWo[d][oo0];
            acc[0][0] += a0 * w.x; acc[0][1] += a0 * w.y; acc[0][2] += a0 * w.z; acc[0][3] += a0 * w.w;
            acc[1][0] += a1 * w.x; acc[1][1] += a1 * w.y; acc[1][2] += a1 * w.z; acc[1][3] += a1 * w.w;
            acc[2][0] += a2 * w.x; acc[2][1] += a2 * w.y; acc[2][2] += a2 * w.z; acc[2][3] += a2 * w.w;
            acc[3][0] += a3 * w.x; acc[3][1] += a3 * w.y; acc[3][2] += a3 * w.z; acc[3][3] += a3 * w.w;
        }
        #pragma unroll
        for (int u = 0; u < 4; u++) {
            float4 o4 = make_float4(acc[u][0], acc[u][1], acc[u][2], acc[u][3]);
            *(float4*)(g_VW + (size_t)(h * Nn + j0 + jj0 + u) * DNn + oo0) = o4;
        }
    }
}

// ================= kernel C: edge_mega v3 (unchanged) =================
#define EMS_SIM  0
#define EMS_QEP  4096
#define EMS_SINV 4608
#define EMS_RED  4624
#define EMS_E    8720
#define EM_SMEM  ((EMS_E + 64 * 68 + 32) * 4)

__global__ void __launch_bounds__(256, 4)
edge_mega_kernel(const float* __restrict__ edges)
{
    extern __shared__ float sm[];
    float* sSim  = sm + EMS_SIM;
    ull*   sQEP  = (ull*)(sm + EMS_QEP);
    float* sSinv = sm + EMS_SINV;
    ull*   sRed  = (ull*)(sm + EMS_RED);
    float* sE    = sm + EMS_E;

    const int i = blockIdx.x;
    const int t = threadIdx.x;
    const int w = t >> 5, l = t & 31;

    #pragma unroll
    for (int r = 0; r < 4; r++) {
        int idx = t + 256 * r;
        int h = idx >> 7, j4 = (idx & 127) * 4;
        *(float4*)&sSim[h * 512 + j4] = *(const float4*)(g_sim + ((size_t)(h * Nn + i)) * Nn + j4);
    }
    {
        int c = t >> 2, hp = t & 3;
        float a = g_qe[(size_t)(2 * hp)     * (Nn * DEn) + (size_t)i * DEn + c];
        float b = g_qe[(size_t)(2 * hp + 1) * (Nn * DEn) + (size_t)i * DEn + c];
        sQEP[c * 4 + hp] = pk2(a, b);
    }
    __syncthreads();

    const int ce0 = w * 8;
    const int rot0 = EROT(l);

    for (int tile = 0; tile < 8; tile++) {
        const int j0 = tile * 64;
        #pragma unroll
        for (int u = 0; u < 4; u++) {
            int idx = t + 256 * u;
            int row = idx >> 4, s4 = (idx & 15) * 4;
            *(float4*)&sE[row * 68 + ((s4 + EROT(row)) & 63)] =
                *(const float4*)(edges + ((size_t)i * Nn + j0 + row) * DEn + s4);
        }
        __syncthreads();

        ull a0[4] = {0, 0, 0, 0}, a1[4] = {0, 0, 0, 0};
        #pragma unroll
        for (int cc = 0; cc < 2; cc++) {
            const int cb = ce0 + cc * 4;
            const int co = (cb + rot0) & 63;
            float4 e0 = *(const float4*)&sE[l * 68 + co];
            float4 e1 = *(const float4*)&sE[(l + 32) * 68 + co];
            float e0a[4] = {e0.x, e0.y, e0.z, e0.w};
            float e1a[4] = {e1.x, e1.y, e1.z, e1.w};
            #pragma unroll
            for (int k = 0; k < 4; k++) {
                ulonglong2 q01 = *(const ulonglong2*)&sQEP[(cb + k) * 4];
                ulonglong2 q23 = *(const ulonglong2*)&sQEP[(cb + k) * 4 + 2];
                ull ed0 = pk2(e0a[k], e0a[k]);
                ull ed1 = pk2(e1a[k], e1a[k]);
                fma2(a0[0], ed0, q01.x); fma2(a0[1], ed0, q01.y);
                fma2(a0[2], ed0, q23.x); fma2(a0[3], ed0, q23.y);
                fma2(a1[0], ed1, q01.x); fma2(a1[1], ed1, q01.y);
                fma2(a1[2], ed1, q23.x); fma2(a1[3], ed1, q23.y);
            }
        }
        #pragma unroll
        for (int hp = 0; hp < 4; hp++) {
            sRed[w * 256 + hp * 64 + l]      = a0[hp];
            sRed[w * 256 + hp * 64 + l + 32] = a1[hp];
        }
        __syncthreads();

        {
            const int rr = t & 63, hp2 = t >> 6;
            float ax = 0.f, ay = 0.f;
            #pragma unroll
            for (int qq = 0; qq < 8; qq++) {
                float2 f = upk2(sRed[qq * 256 + hp2 * 64 + rr]);
                ax += f.x; ay += f.y;
            }
            sSim[(2 * hp2) * 512 + j0 + rr]     += ax;
            sSim[(2 * hp2 + 1) * 512 + j0 + rr] += ay;
        }
        __syncthreads();
    }

    {
        float vals[16];
        float mx = -1e30f;
        #pragma unroll
        for (int jc = 0; jc < 16; jc++) {
            vals[jc] = sSim[w * 512 + jc * 32 + l];
            mx = fmaxf(mx, vals[jc]);
        }
        #pragma unroll
        for (int off = 16; off > 0; off >>= 1) mx = fmaxf(mx, __shfl_xor_sync(0xffffffffu, mx, off));
        float s = 0.f;
        #pragma unroll
        for (int jc = 0; jc < 16; jc++) {
            float e = __expf(vals[jc] - mx);
            s += e;
            sSim[w * 512 + jc * 32 + l] = e;
        }
        #pragma unroll
        for (int off = 16; off > 0; off >>= 1) s += __shfl_xor_sync(0xffffffffu, s, off);
        if (l == 0) sSinv[w] = 1.0f / s;
    }
    __syncthreads();

    #pragma unroll
    for (int r = 0; r < 4; r++) {
        int idx = t + 256 * r;
        int h = idx >> 7, j4 = (idx & 127) * 4;
        float4 v = *(const float4*)&sSim[h * 512 + j4];
        float s = sSinv[h];
        v.x *= s; v.y *= s; v.z *= s; v.w *= s;
        *(float4*)(g_sim + ((size_t)(h * Nn + i)) * Nn + j4) = v;
    }

    {
        float pr[16];
        #pragma unroll
        for (int h = 0; h < 8; h++) {
            pr[h]     = sSim[h * 512 + t];
            pr[8 + h] = sSim[h * 512 + t + 256];
        }
        __syncthreads();
        ull* sPP = (ull*)sSim;
        #pragma unroll
        for (int hp = 0; hp < 4; hp++) {
            sPP[t * 4 + hp]         = pk2(pr[2 * hp],     pr[2 * hp + 1]);
            sPP[(t + 256) * 4 + hp] = pk2(pr[8 + 2 * hp], pr[8 + 2 * hp + 1]);
        }
    }
    __syncthreads();

    {
        ull* sPP = (ull*)sSim;
        ull acc[4][2];
        #pragma unroll
        for (int hp = 0; hp < 4; hp++) { acc[hp][0] = 0ull; acc[hp][1] = 0ull; }

        for (int tile = 0; tile < 8; tile++) {
            const int j0 = tile * 64;
            #pragma unroll
            for (int u = 0; u < 4; u++) {
                int idx = t + 256 * u;
                int row = idx >> 4, s4 = (idx & 15) * 4;
                *(float4*)&sE[row * 68 + ((s4 + EROT(row)) & 63)] =
                    *(const float4*)(edges + ((size_t)i * Nn + j0 + row) * DEn + s4);
            }
            __syncthreads();

            const int jb = w * 8;
            #pragma unroll
            for (int jj = 0; jj < 8; jj++) {
                const int j = jb + jj;
                ull e2 = *(const ull*)&sE[j * 68 + ((2 * l + EROT(j)) & 63)];
                float2 ef = upk2(e2);
                ull e0 = pk2(ef.x, ef.x);
                ull e1 = pk2(ef.y, ef.y);
                const ull* pp = sPP + (size_t)(j0 + j) * 4;
                fma2(acc[0][0], pp[0], e0); fma2(acc[0][1], pp[0], e1);
                fma2(acc[1][0], pp[1], e0); fma2(acc[1][1], pp[1], e1);
                fma2(acc[2][0], pp[2], e0); fma2(acc[2][1], pp[2], e1);
                fma2(acc[3][0], pp[3], e0); fma2(acc[3][1], pp[3], e1);
            }
            __syncthreads();
        }

        #pragma unroll
        for (int hp = 0; hp < 4; hp++) {
            sRed[w * 256 + l * 8 + hp * 2 + 0] = acc[hp][0];
            sRed[w * 256 + l * 8 + hp * 2 + 1] = acc[hp][1];
        }
        __syncthreads();

        {
            float ax = 0.f, ay = 0.f;
            #pragma unroll
            for (int ww = 0; ww < 8; ww++) {
                float2 f = upk2(sRed[ww * 256 + t]);
                ax += f.x; ay += f.y;
            }
            const int c  = 2 * (t >> 3) + (t & 1);
            const int h0 = 2 * ((t >> 1) & 3);
            g_ew[(size_t)h0       * (Nn * DEn) + (size_t)i * DEn + c] = ax * sSinv[h0];
            g_ew[(size_t)(h0 + 1) * (Nn * DEn) + (size_t)i * DEn + c] = ay * sSinv[h0 + 1];
        }
    }
}

// ================= kernel D: epilogue GEMM v7 (R13 microkernel + reg prefetch) ====
#define G7_A 0                        // sA[32][68]
#define G7_B (32 * 68)                // sB[64][132]
#define G7_SMEM ((G7_B + 64 * 132) * 4)

__global__ void __launch_bounds__(256)
gemm_out_kernel()
{
    extern __shared__ float gsm[];
    float* sA = gsm + G7_A;
    float* sB = gsm + G7_B;

    const int t  = threadIdx.x;
    const int i0 = blockIdx.x * 32;
    const int h  = blockIdx.y >> 1;
    const int kh = blockIdx.y & 1;

    const int warp = t >> 5, lane = t & 31;
    const int ib = warp * 4;
    const int ob = lane * 4;

    // staging indices
    const int aI  = t >> 4, aK4 = (t & 15) * 4;        // A: 2 rows per thread (aI, aI+16... no: u loop)
    const int bK  = t >> 5, bO4 = (t & 31) * 4;        // B: 8 rows per thread via u loop

    ull acc[4][2];
    #pragma unroll
    for (int r = 0; r < 4; r++) { acc[r][0] = 0ull; acc[r][1] = 0ull; }

    const int kcs = kh ? 4 : 0;
    const int kce = kh ? 9 : 4;

    float4 av[2], bv[8];

    // prefetch first tile
    {
        const int kc = kcs;
        #pragma unroll
        for (int u = 0; u < 2; u++) {
            int i = aI + 16 * u;
            if (kc < 8) av[u] = *(const float4*)(g_sim + ((size_t)(h * Nn + i0 + i)) * Nn + kc * 64 + aK4);
            else        av[u] = *(const float4*)(g_ew + (size_t)h * (Nn * DEn) + (size_t)(i0 + i) * DEn + aK4);
        }
        #pragma unroll
        for (int u = 0; u < 8; u++) {
            int k = bK + 8 * u;
            if (kc < 8) bv[u] = *(const float4*)(g_VW + ((size_t)(h * Nn + kc * 64 + k)) * DNn + bO4);
            else        bv[u] = *(const float4*)(g_M + ((size_t)(h * 64 + k)) * DNn + bO4);
        }
    }

    for (int kc = kcs; kc < kce; kc++) {
        // store staged tile
        #pragma unroll
        for (int u = 0; u < 2; u++)
            *(float4*)&sA[(aI + 16 * u) * 68 + aK4] = av[u];
        #pragma unroll
        for (int u = 0; u < 8; u++)
            *(float4*)&sB[(bK + 8 * u) * 132 + bO4] = bv[u];
        __syncthreads();

        // prefetch next tile (overlaps compute)
        if (kc + 1 < kce) {
            const int kn = kc + 1;
            #pragma unroll
            for (int u = 0; u < 2; u++) {
                int i = aI + 16 * u;
                if (kn < 8) av[u] = *(const float4*)(g_sim + ((size_t)(h * Nn + i0 + i)) * Nn + kn * 64 + aK4);
                else        av[u] = *(const float4*)(g_ew + (size_t)h * (Nn * DEn) + (size_t)(i0 + i) * DEn + aK4);
            }
            #pragma unroll
            for (int u = 0; u < 8; u++) {
                int k = bK + 8 * u;
                if (kn < 8) bv[u] = *(const float4*)(g_VW + ((size_t)(h * Nn + kn * 64 + k)) * DNn + bO4);
                else        bv[u] = *(const float4*)(g_M + ((size_t)(h * 64 + k)) * DNn + bO4);
            }
        }

        #pragma unroll 4
        for (int k = 0; k < 64; k++) {
            ulonglong2 bb = *(const ulonglong2*)&sB[k * 132 + ob];
            #pragma unroll
            for (int r = 0; r < 4; r++) {
                float a = sA[(ib + r) * 68 + k];
                ull ad = pk2(a, a);
                fma2(acc[r][0], ad, bb.x);
                fma2(acc[r][1], ad, bb.y);
            }
        }
        __syncthreads();
    }

    float* pp = g_part + (size_t)blockIdx.y * (Nn * DNn);
    #pragma unroll
    for (int r = 0; r < 4; r++) {
        float2 f0 = upk2(acc[r][0]);
        float2 f1 = upk2(acc[r][1]);
        *(float2*)(pp + (size_t)(i0 + ib + r) * DNn + ob)     = f0;
        *(float2*)(pp + (size_t)(i0 + ib + r) * DNn + ob + 2) = f1;
    }
}

// ================= kernel E: reduce 16 partials + bvec =================
__global__ void __launch_bounds__(256)
reduce_out_kernel(float* __restrict__ out)
{
    const int idx = blockIdx.x * 256 + threadIdx.x;
    float a0 = 0.f, a1 = 0.f, a2 = 0.f, a3 = 0.f;
    #pragma unroll
    for (int s = 0; s < 16; s += 4) {
        a0 += g_part[(size_t)s       * (Nn * DNn) + idx];
        a1 += g_part[(size_t)(s + 1) * (Nn * DNn) + idx];
        a2 += g_part[(size_t)(s + 2) * (Nn * DNn) + idx];
        a3 += g_part[(size_t)(s + 3) * (Nn * DNn) + idx];
    }
    out[idx] = (a0 + a1) + (a2 + a3) + g_bvec[idx & 127];
}

// ---------------- launch ----------------
extern "C" void kernel_launch(void* const* d_in, const int* in_sizes, int n_in,
                              void* d_out, int out_size)
{
    const float* nodes = (const float*)d_in[0];
    const float* edges = (const float*)d_in[1];
    const float* Wq = (const float*)d_in[3];
    const float* bq = (const float*)d_in[4];
    const float* Wk = (const float*)d_in[5];
    const float* bk = (const float*)d_in[6];
    const float* Wv = (const float*)d_in[7];
    const float* bv = (const float*)d_in[8];
    const float* We = (const float*)d_in[9];
    const float* be = (const float*)d_in[10];
    const float* Wo = (const float*)d_in[11];
    const float* bo = (const float*)d_in[12];
    float* out = (float*)d_out;

    cudaFuncSetAttribute(edge_mega_kernel, cudaFuncAttributeMaxDynamicSharedMemorySize, EM_SMEM);
    cudaFuncSetAttribute(gemm_out_kernel, cudaFuncAttributeMaxDynamicSharedMemorySize, G7_SMEM);

    qkv_mb_kernel<<<449, 256>>>(nodes, Wq, bq, Wk, bk, Wv, bv, We, be, Wo, bo);
    qksim_vw_kernel<<<640, 256>>>(Wo);
    edge_mega_kernel<<<Nn, 256, EM_SMEM>>>(edges);
    gemm_out_kernel<<<dim3(16, 16), 256, G7_SMEM>>>();
    reduce_out_kernel<<<(Nn * DNn) / 256, 256>>>(out);
}